// round 2
// baseline (speedup 1.0000x reference)
#include <cuda_runtime.h>

// QuantLinear: y[64,4096] = x[64,11008] @ dequant(W)[4096,11008]^T + bias
//
// Dequant (Q4K-style): value j (= o*IN_F + k):
//   byte = packed[j/2]; q = (j even) ? byte&15 : (byte>>4)&15
//   s = j>>8 (super), si = j>>5 (sub-block scale index)
//   w = (q/15 * scales[si]/63 + mins[si]/63) * d[s] + dmin[s]
//     = q*A + B,  A = d*scales[si]/(63*15),  B = d*mins[si]/63 + dmin
//
// Structure: CTA computes a 64(M) x 64(N) output tile over K/2 (K-split=2),
// BK=32 = exactly one sub-block (one scale fetch per row per chunk).
// Register-prefetch pipeline; smem staged transposed for LDS.128 reads;
// fma.rn.f32x2 packed FMAs along the M dimension.
// Deterministic split-K: partials to __device__ scratch, reduce kernel adds bias.

#define OUT_F 4096
#define IN_F  11008
#define MROWS 64
#define BN    64
#define BK    32
#define KSPLIT 2
#define KC    (IN_F / KSPLIT)   // 5504
#define NCHUNK (KC / BK)        // 172

typedef unsigned long long u64;

__device__ float g_part[KSPLIT][MROWS * OUT_F];   // 2 MB static scratch (allowed)

__device__ __forceinline__ u64 pk2(float a, float b) {
    u64 r; asm("mov.b64 %0, {%1, %2};" : "=l"(r) : "f"(a), "f"(b)); return r;
}
__device__ __forceinline__ void upk2(u64 v, float& a, float& b) {
    asm("mov.b64 {%0, %1}, %2;" : "=f"(a), "=f"(b) : "l"(v));
}
__device__ __forceinline__ void fma2(u64& d, u64 a, u64 b) {
    asm("fma.rn.f32x2 %0, %1, %2, %0;" : "+l"(d) : "l"(a), "l"(b));
}

__global__ __launch_bounds__(256, 1)
void qlinear_kernel(const float* __restrict__ x,
                    const int*   __restrict__ packed,
                    const float* __restrict__ d,
                    const float* __restrict__ dmin,
                    const int*   __restrict__ scales,
                    const int*   __restrict__ mins)
{
    __shared__ float xsT[BK][MROWS];  // [k][m]
    __shared__ float wsT[BK][BN];     // [k][n_local]

    const int t  = threadIdx.x;
    const int ob = blockIdx.x & 63;        // N tile
    const int ks = blockIdx.x >> 6;        // K split half
    const int o0 = ob * BN;

    // staging role: 4 threads per row, 8 values each
    const int row = t >> 2;                // 0..63 (m row for x, n row for w)
    const int c   = t & 3;                 // quarter of the 32-k chunk

    // fma role: 16x16 thread grid, 4x4 register tile
    const int tx = t & 15, ty = t >> 4;
    const int tn = tx * 4, tm = ty * 4;

    u64 acc[4][2];
#pragma unroll
    for (int j = 0; j < 4; j++) { acc[j][0] = 0ULL; acc[j][1] = 0ULL; }

    const int kbase = ks * KC;
    const int orow  = o0 + row;

    // prefetch registers
    float4 xa, xb; int4 pw; float A, B;

    auto LOAD = [&](int chunk) {
        const int k0 = kbase + chunk * BK;
        // x: row 'row', 8 consecutive k starting at c*8 (two float4s)
        const float* xp = x + row * IN_F + k0 + c * 8;
        xa = *(const float4*)(xp);
        xb = *(const float4*)(xp + 4);
        // w scales for this row's sub-block
        const int j0 = orow * IN_F + k0;       // < 2^26, fits int
        const int si = j0 >> 5;                // sub-block scale index
        const int sp = j0 >> 8;                // super index
        const float dd = d[sp];
        const float dm = dmin[sp];
        const float sc = (float)scales[si] * (1.0f / 63.0f);
        const float mn = (float)mins[si]   * (1.0f / 63.0f);
        A = dd * sc * (1.0f / 15.0f);
        B = fmaf(dd, mn, dm);
        // packed: 16 int32 per (row, 32-k chunk); this thread takes 4 of them
        pw = *(const int4*)(packed + orow * (IN_F / 2) + (k0 >> 1) + c * 4);
    };

    auto STAGE = [&]() {
        const int kk = c * 8;
        xsT[kk + 0][row] = xa.x; xsT[kk + 1][row] = xa.y;
        xsT[kk + 2][row] = xa.z; xsT[kk + 3][row] = xa.w;
        xsT[kk + 4][row] = xb.x; xsT[kk + 5][row] = xb.y;
        xsT[kk + 6][row] = xb.z; xsT[kk + 7][row] = xb.w;
        int pv[4] = { pw.x, pw.y, pw.z, pw.w };
#pragma unroll
        for (int ii = 0; ii < 4; ii++) {
            const int b = pv[ii];
            const float lo = (float)(b & 15);
            const float hi = (float)((b >> 4) & 15);
            wsT[kk + ii * 2    ][row] = fmaf(lo, A, B);
            wsT[kk + ii * 2 + 1][row] = fmaf(hi, A, B);
        }
    };

    LOAD(0);
    for (int chunk = 0; chunk < NCHUNK; chunk++) {
        STAGE();
        __syncthreads();
        if (chunk + 1 < NCHUNK) LOAD(chunk + 1);   // prefetch hides LDG latency
#pragma unroll
        for (int kk = 0; kk < BK; kk++) {
            const float4 xv = *(const float4*)&xsT[kk][tm];
            const float4 wv = *(const float4*)&wsT[kk][tn];
            const u64 x01 = pk2(xv.x, xv.y);
            const u64 x23 = pk2(xv.z, xv.w);
            u64 w;
            w = pk2(wv.x, wv.x); fma2(acc[0][0], x01, w); fma2(acc[0][1], x23, w);
            w = pk2(wv.y, wv.y); fma2(acc[1][0], x01, w); fma2(acc[1][1], x23, w);
            w = pk2(wv.z, wv.z); fma2(acc[2][0], x01, w); fma2(acc[2][1], x23, w);
            w = pk2(wv.w, wv.w); fma2(acc[3][0], x01, w); fma2(acc[3][1], x23, w);
        }
        __syncthreads();
    }

    // write partials (each (ks, m, o) written exactly once -> deterministic)
    float* part = &g_part[ks][0];
#pragma unroll
    for (int j = 0; j < 4; j++) {
        const int o = o0 + tn + j;
        float v0, v1, v2, v3;
        upk2(acc[j][0], v0, v1);
        upk2(acc[j][1], v2, v3);
        part[(tm + 0) * OUT_F + o] = v0;
        part[(tm + 1) * OUT_F + o] = v1;
        part[(tm + 2) * OUT_F + o] = v2;
        part[(tm + 3) * OUT_F + o] = v3;
    }
}

__global__ void reduce_kernel(const float* __restrict__ bias,
                              float* __restrict__ out)
{
    const int i = blockIdx.x * blockDim.x + threadIdx.x;
    if (i < MROWS * OUT_F) {
        out[i] = bias[i & (OUT_F - 1)] + g_part[0][i] + g_part[1][i];
    }
}

extern "C" void kernel_launch(void* const* d_in, const int* in_sizes, int n_in,
                              void* d_out, int out_size)
{
    const float* x      = (const float*)d_in[0];
    const int*   packed = (const int*)  d_in[1];
    const float* d      = (const float*)d_in[2];
    const float* dmin   = (const float*)d_in[3];
    const int*   scales = (const int*)  d_in[4];
    const int*   mins   = (const int*)  d_in[5];
    const float* bias   = (const float*)d_in[6];
    float* out = (float*)d_out;

    qlinear_kernel<<<64 * KSPLIT, 256>>>(x, packed, d, dmin, scales, mins);
    reduce_kernel<<<(MROWS * OUT_F + 255) / 256, 256>>>(bias, out);
}

// round 6
// speedup vs baseline: 3.5600x; 3.5600x over previous
#include <cuda_runtime.h>
#include <cuda_fp16.h>
#include <cstdint>

// y[64,4096] = x[64,11008] @ dequant(W)[4096,11008]^T + bias
// mma.sync.m16n8k16 (HMMA) f16 inputs / fp32 accum; W dequanted LDG->registers
// directly into B fragments; x staged to swizzled smem, read via ldmatrix.
// Grid: 32 o-tiles x KSPLIT(4) = 128 CTAs x 256 threads (8 warps, n16/warp).

#define OUT_F  4096
#define IN_F   11008
#define MROWS  64
#define BN     128
#define BK     64
#define KSPLIT 4
#define KC     (IN_F / KSPLIT)     // 2752
#define NCHUNK (KC / BK)           // 43
#define NTILES (OUT_F / BN)        // 32
#define THREADS 256

__device__ float g_part[KSPLIT][MROWS * OUT_F];   // [ks][m][o] partials (4 MB)

__device__ __forceinline__ uint32_t swz(uint32_t o) { return o ^ ((o >> 3) & 0x70); }

__device__ __forceinline__ uint32_t pkh2(float lo, float hi) {
    uint32_t r;
    asm("cvt.rn.f16x2.f32 %0, %1, %2;" : "=r"(r) : "f"(hi), "f"(lo));
    return r;
}

__device__ __forceinline__ void mma16816(float* c, const uint32_t* a,
                                         uint32_t b0, uint32_t b1) {
    asm volatile(
        "mma.sync.aligned.m16n8k16.row.col.f32.f16.f16.f32 "
        "{%0,%1,%2,%3}, {%4,%5,%6,%7}, {%8,%9}, {%0,%1,%2,%3};"
        : "+f"(c[0]), "+f"(c[1]), "+f"(c[2]), "+f"(c[3])
        : "r"(a[0]), "r"(a[1]), "r"(a[2]), "r"(a[3]), "r"(b0), "r"(b1));
}

__device__ __forceinline__ void ldsm4(uint32_t* r, uint32_t addr) {
    asm volatile("ldmatrix.sync.aligned.m8n8.x4.shared.b16 {%0,%1,%2,%3}, [%4];"
                 : "=r"(r[0]), "=r"(r[1]), "=r"(r[2]), "=r"(r[3]) : "r"(addr));
}

struct Pref {
    int    pw[16];            // 8 int32 per n8-tile row (2 rows/lane)
    float4 x0, x1, x2, x3;    // 16 x floats
    int    sca0, sca1, mna0, mna1;   // row r0: sub-blocks 0,1
    int    scb0, scb1, mnb0, mnb1;   // row r1
    float  da, dma, db, dmb;         // supers (both sub-blocks share one super)
};

__global__ __launch_bounds__(THREADS, 1)
void qmma_kernel(const float* __restrict__ x,
                 const int*   __restrict__ packed,
                 const float* __restrict__ d,
                 const float* __restrict__ dmin,
                 const int*   __restrict__ scales,
                 const int*   __restrict__ mins)
{
    __shared__ __align__(1024) char xs[2][MROWS * 128];   // 2 x 8KB f16 x-tiles

    const int t    = threadIdx.x;
    const int lane = t & 31;
    const int w    = t >> 5;                 // 8 warps, n16 each
    const int ob   = blockIdx.x & (NTILES - 1);
    const int ks   = blockIdx.x >> 5;
    const int o0   = ob * BN;
    const int kbase = ks * KC;               // multiple of 64

    // x staging role: thread -> (row, 16-float quarter)
    const int xm = t >> 2, xq = t & 3;
    const float* xrow = x + xm * IN_F + kbase + xq * 16;
    const uint32_t xoff = xm * 128 + xq * 32;

    // W role: lane covers rows r0 (n-tile 0) and r0+8 (n-tile 1), k-quad kq
    const int r0 = o0 + w * 16 + (lane >> 2);
    const int kq = lane & 3;
    const int* prow0 = packed + r0 * (IN_F / 2) + (kbase >> 1) + kq;
    const int* prow1 = prow0 + 8 * (IN_F / 2);

    float acc[4][2][4];
#pragma unroll
    for (int mt = 0; mt < 4; mt++)
#pragma unroll
        for (int nt = 0; nt < 2; nt++)
#pragma unroll
            for (int i = 0; i < 4; i++) acc[mt][nt][i] = 0.f;

    Pref ra, rb;

    auto LOADR = [&](int c, Pref& r) {
        const int cb = c * 32;
#pragma unroll
        for (int j = 0; j < 8; j++) {
            r.pw[j]     = __ldg(prow0 + cb + 4 * j);
            r.pw[8 + j] = __ldg(prow1 + cb + 4 * j);
        }
        const float4* xp = (const float4*)(xrow + c * BK);
        r.x0 = xp[0]; r.x1 = xp[1]; r.x2 = xp[2]; r.x3 = xp[3];
        const int j0 = r0 * IN_F + kbase + c * BK;        // mult of 64
        const int j1 = j0 + 8 * IN_F;
        const int si0 = j0 >> 5, sp0 = j0 >> 8;
        const int si1 = j1 >> 5, sp1 = j1 >> 8;
        r.sca0 = scales[si0]; r.sca1 = scales[si0 + 1];
        r.mna0 = mins[si0];   r.mna1 = mins[si0 + 1];
        r.da = d[sp0];        r.dma = dmin[sp0];
        r.scb0 = scales[si1]; r.scb1 = scales[si1 + 1];
        r.mnb0 = mins[si1];   r.mnb1 = mins[si1 + 1];
        r.db = d[sp1];        r.dmb = dmin[sp1];
    };

    auto STAGE = [&](const Pref& r, int buf) {
        char* b = xs[buf];
        uint4 v0 = make_uint4(pkh2(r.x0.x, r.x0.y), pkh2(r.x0.z, r.x0.w),
                              pkh2(r.x1.x, r.x1.y), pkh2(r.x1.z, r.x1.w));
        uint4 v1 = make_uint4(pkh2(r.x2.x, r.x2.y), pkh2(r.x2.z, r.x2.w),
                              pkh2(r.x3.x, r.x3.y), pkh2(r.x3.z, r.x3.w));
        *(uint4*)(b + swz(xoff))      = v0;
        *(uint4*)(b + swz(xoff + 16)) = v1;
    };

    // magic-bias dequant: q|0x4B000000 as float = 8388608+q
    auto DEQF = [](int b, int sh) -> float {
        return __int_as_float(((b >> sh) ? 0 : 0, (b & (15 << sh)) | 0x4B000000));
    };
    (void)DEQF;

    auto COMPUTE = [&](const Pref& r, int buf) {
        // coefficients: w = q*A + B; hi nibble keeps factor 16 -> Ah = A/16
        const float Aa0 = r.da * (float)r.sca0 * (1.f / 945.f);
        const float Aa1 = r.da * (float)r.sca1 * (1.f / 945.f);
        const float Ba0 = fmaf(r.da, (float)r.mna0 * (1.f / 63.f), r.dma);
        const float Ba1 = fmaf(r.da, (float)r.mna1 * (1.f / 63.f), r.dma);
        const float Ab0 = r.db * (float)r.scb0 * (1.f / 945.f);
        const float Ab1 = r.db * (float)r.scb1 * (1.f / 945.f);
        const float Bb0 = fmaf(r.db, (float)r.mnb0 * (1.f / 63.f), r.dmb);
        const float Bb1 = fmaf(r.db, (float)r.mnb1 * (1.f / 63.f), r.dmb);

        uint32_t bfr[2][8];
#pragma unroll
        for (int j = 0; j < 8; j++) {
            const float A  = (j < 4) ? Aa0 : Aa1;
            const float B  = (j < 4) ? Ba0 : Ba1;
            const int   b  = r.pw[j];
            const float lo = __int_as_float((b & 15)   | 0x4B000000) - 8388608.f;
            const float hi = __int_as_float((b & 0xF0) | 0x4B000000) - 8388608.f;
            bfr[0][j] = pkh2(fmaf(lo, A, B), fmaf(hi, A * 0.0625f, B));
        }
#pragma unroll
        for (int j = 0; j < 8; j++) {
            const float A  = (j < 4) ? Ab0 : Ab1;
            const float B  = (j < 4) ? Bb0 : Bb1;
            const int   b  = r.pw[8 + j];
            const float lo = __int_as_float((b & 15)   | 0x4B000000) - 8388608.f;
            const float hi = __int_as_float((b & 0xF0) | 0x4B000000) - 8388608.f;
            bfr[1][j] = pkh2(fmaf(lo, A, B), fmaf(hi, A * 0.0625f, B));
        }

        const uint32_t su = (uint32_t)__cvta_generic_to_shared(xs[buf]);
        const uint32_t lrow = (lane & 15) * 128 + (lane >> 4) * 16;
#pragma unroll
        for (int s = 0; s < 4; s++) {
            uint32_t a[4][4];
#pragma unroll
            for (int mt = 0; mt < 4; mt++)
                ldsm4(a[mt], su + swz(mt * 2048 + lrow + s * 32));
#pragma unroll
            for (int mt = 0; mt < 4; mt++) {
                mma16816(acc[mt][0], a[mt], bfr[0][2 * s], bfr[0][2 * s + 1]);
                mma16816(acc[mt][1], a[mt], bfr[1][2 * s], bfr[1][2 * s + 1]);
            }
        }
    };

    LOADR(0, ra);
    STAGE(ra, 0);
    __syncthreads();
#pragma unroll 1
    for (int c = 0; c < NCHUNK; c++) {
        const bool more = (c + 1 < NCHUNK);
        if (more) LOADR(c + 1, rb);
        COMPUTE(ra, c & 1);
        if (more) STAGE(rb, (c + 1) & 1);
        __syncthreads();
        ra = rb;
    }

    // write partials: frag (m,n) mapping of m16n8k16 C
    float* part = g_part[ks];
#pragma unroll
    for (int mt = 0; mt < 4; mt++) {
        const int m = mt * 16 + (lane >> 2);
#pragma unroll
        for (int nt = 0; nt < 2; nt++) {
            const int n = o0 + w * 16 + nt * 8 + (lane & 3) * 2;
            *(float2*)&part[m * OUT_F + n] =
                make_float2(acc[mt][nt][0], acc[mt][nt][1]);
            *(float2*)&part[(m + 8) * OUT_F + n] =
                make_float2(acc[mt][nt][2], acc[mt][nt][3]);
        }
    }
}

__global__ __launch_bounds__(256)
void reduce_kernel(const float* __restrict__ bias, float* __restrict__ out)
{
    const int i = blockIdx.x * 256 + threadIdx.x;       // float4 index
    const float4 bb = ((const float4*)bias)[i & (OUT_F / 4 - 1)];
    float4 s = bb;
#pragma unroll
    for (int ks = 0; ks < KSPLIT; ks++) {
        const float4 p = ((const float4*)g_part[ks])[i];
        s.x += p.x; s.y += p.y; s.z += p.z; s.w += p.w;
    }
    ((float4*)out)[i] = s;
}

extern "C" void kernel_launch(void* const* d_in, const int* in_sizes, int n_in,
                              void* d_out, int out_size)
{
    const float* x      = (const float*)d_in[0];
    const int*   packed = (const int*)  d_in[1];
    const float* d      = (const float*)d_in[2];
    const float* dmin   = (const float*)d_in[3];
    const int*   scales = (const int*)  d_in[4];
    const int*   mins   = (const int*)  d_in[5];
    const float* bias   = (const float*)d_in[6];
    float* out = (float*)d_out;

    qmma_kernel<<<NTILES * KSPLIT, THREADS>>>(x, packed, d, dmin, scales, mins);
    reduce_kernel<<<(MROWS * OUT_F / 4) / 256, 256>>>(bias, out);
}

// round 7
// speedup vs baseline: 4.5858x; 1.2881x over previous
#include <cuda_runtime.h>
#include <cuda_fp16.h>
#include <cstdint>

// y[64,4096] = x[64,11008] @ dequant(W)[4096,11008]^T + bias
// mma.sync.m16n8k16 f16/fp32. W: LDG->dequant->B-fragments (no smem).
// x: pre-converted to f16 (g_xh), staged via cp.async 4-stage ring.
// W loads prefetched distance 2 in registers. KSPLIT=4 deterministic partials.

#define OUT_F  4096
#define IN_F   11008
#define MROWS  64
#define BN     128
#define BK     64
#define KSPLIT 4
#define KC     (IN_F / KSPLIT)     // 2752
#define NCHUNK (KC / BK)           // 43
#define NTILES (OUT_F / BN)        // 32
#define THREADS 256
#define STAGES 4
#define STAGE_BYTES (MROWS * 128)  // 8KB: 64 rows x 64 f16

__device__ float g_part[KSPLIT][MROWS * OUT_F];            // 4 MB
__device__ __align__(16) __half g_xh[MROWS * IN_F];        // 1.4 MB f16 x

__device__ __forceinline__ uint32_t swz(uint32_t o) { return o ^ ((o >> 3) & 0x70); }

__device__ __forceinline__ uint32_t pkh2(float lo, float hi) {
    uint32_t r;
    asm("cvt.rn.f16x2.f32 %0, %1, %2;" : "=r"(r) : "f"(hi), "f"(lo));
    return r;
}
__device__ __forceinline__ void cpa16(uint32_t dst, const void* src) {
    asm volatile("cp.async.cg.shared.global [%0], [%1], 16;"
                 :: "r"(dst), "l"(src) : "memory");
}
__device__ __forceinline__ void cpa_commit() {
    asm volatile("cp.async.commit_group;" ::: "memory");
}
__device__ __forceinline__ void cpa_wait2() {
    asm volatile("cp.async.wait_group 2;" ::: "memory");
}
__device__ __forceinline__ void mma16816(float* c, const uint32_t* a,
                                         uint32_t b0, uint32_t b1) {
    asm volatile(
        "mma.sync.aligned.m16n8k16.row.col.f32.f16.f16.f32 "
        "{%0,%1,%2,%3}, {%4,%5,%6,%7}, {%8,%9}, {%0,%1,%2,%3};"
        : "+f"(c[0]), "+f"(c[1]), "+f"(c[2]), "+f"(c[3])
        : "r"(a[0]), "r"(a[1]), "r"(a[2]), "r"(a[3]), "r"(b0), "r"(b1));
}
__device__ __forceinline__ void ldsm4(uint32_t* r, uint32_t addr) {
    asm volatile("ldmatrix.sync.aligned.m8n8.x4.shared.b16 {%0,%1,%2,%3}, [%4];"
                 : "=r"(r[0]), "=r"(r[1]), "=r"(r[2]), "=r"(r[3]) : "r"(addr));
}

struct PrefW {
    int   pw[16];                       // 8 int32 per n8-row, 2 rows/lane
    int   sca0, sca1, mna0, mna1;       // row r0 sub-blocks
    int   scb0, scb1, mnb0, mnb1;       // row r0+8 sub-blocks
    float da, dma, db, dmb;
};

__global__ __launch_bounds__(THREADS, 1)
void qmma_kernel(const int*   __restrict__ packed,
                 const float* __restrict__ d,
                 const float* __restrict__ dmin,
                 const int*   __restrict__ scales,
                 const int*   __restrict__ mins)
{
    __shared__ __align__(1024) char xs[STAGES][STAGE_BYTES];   // 32 KB

    const int t    = threadIdx.x;
    const int lane = t & 31;
    const int w    = t >> 5;
    const int ob   = blockIdx.x & (NTILES - 1);
    const int ks   = blockIdx.x >> 5;
    const int o0   = ob * BN;
    const int kbase = ks * KC;

    // cp.async role: 2x 16B per thread per stage
    const int srow = t >> 3, sseg = t & 7;
    const __half* xsrc0 = g_xh + srow * IN_F + kbase + sseg * 8;
    const __half* xsrc1 = xsrc0 + 32 * IN_F;
    const uint32_t xs_u32 = (uint32_t)__cvta_generic_to_shared(&xs[0][0]);
    const uint32_t xdst0 = swz(srow * 128 + sseg * 16);
    const uint32_t xdst1 = swz((srow + 32) * 128 + sseg * 16);

    // W role
    const int r0 = o0 + w * 16 + (lane >> 2);
    const int kq = lane & 3;
    const int* prow0 = packed + r0 * (IN_F / 2) + (kbase >> 1) + kq;
    const int* prow1 = prow0 + 8 * (IN_F / 2);

    float acc[4][2][4];
#pragma unroll
    for (int mt = 0; mt < 4; mt++)
#pragma unroll
        for (int nt = 0; nt < 2; nt++)
#pragma unroll
            for (int i = 0; i < 4; i++) acc[mt][nt][i] = 0.f;

    auto ISSUE = [&](int c) {   // stage = c & 3
        const uint32_t base = xs_u32 + (c & 3) * STAGE_BYTES;
        cpa16(base + xdst0, xsrc0 + c * BK);
        cpa16(base + xdst1, xsrc1 + c * BK);
    };

    auto LOADW = [&](int c, PrefW& r) {
        const int cb = c * 32;
#pragma unroll
        for (int j = 0; j < 8; j++) {
            r.pw[j]     = __ldg(prow0 + cb + 4 * j);
            r.pw[8 + j] = __ldg(prow1 + cb + 4 * j);
        }
        const int j0 = r0 * IN_F + kbase + c * BK;
        const int j1 = j0 + 8 * IN_F;
        const int si0 = j0 >> 5, sp0 = j0 >> 8;
        const int si1 = j1 >> 5, sp1 = j1 >> 8;
        r.sca0 = __ldg(scales + si0); r.sca1 = __ldg(scales + si0 + 1);
        r.mna0 = __ldg(mins + si0);   r.mna1 = __ldg(mins + si0 + 1);
        r.da = __ldg(d + sp0);        r.dma = __ldg(dmin + sp0);
        r.scb0 = __ldg(scales + si1); r.scb1 = __ldg(scales + si1 + 1);
        r.mnb0 = __ldg(mins + si1);   r.mnb1 = __ldg(mins + si1 + 1);
        r.db = __ldg(d + sp1);        r.dmb = __ldg(dmin + sp1);
    };

    auto COMPUTE = [&](const PrefW& r, int stage) {
        const float Aa0 = r.da * (float)r.sca0 * (1.f / 945.f);
        const float Aa1 = r.da * (float)r.sca1 * (1.f / 945.f);
        const float Ba0 = fmaf(r.da, (float)r.mna0 * (1.f / 63.f), r.dma);
        const float Ba1 = fmaf(r.da, (float)r.mna1 * (1.f / 63.f), r.dma);
        const float Ab0 = r.db * (float)r.scb0 * (1.f / 945.f);
        const float Ab1 = r.db * (float)r.scb1 * (1.f / 945.f);
        const float Bb0 = fmaf(r.db, (float)r.mnb0 * (1.f / 63.f), r.dmb);
        const float Bb1 = fmaf(r.db, (float)r.mnb1 * (1.f / 63.f), r.dmb);

        uint32_t bfr[2][8];
#pragma unroll
        for (int j = 0; j < 8; j++) {
            const float A  = (j < 4) ? Aa0 : Aa1;
            const float B  = (j < 4) ? Ba0 : Ba1;
            const int   b  = r.pw[j];
            const float lo = __int_as_float((b & 15)   | 0x4B000000) - 8388608.f;
            const float hi = __int_as_float((b & 0xF0) | 0x4B000000) - 8388608.f;
            bfr[0][j] = pkh2(fmaf(lo, A, B), fmaf(hi, A * 0.0625f, B));
        }
#pragma unroll
        for (int j = 0; j < 8; j++) {
            const float A  = (j < 4) ? Ab0 : Ab1;
            const float B  = (j < 4) ? Bb0 : Bb1;
            const int   b  = r.pw[8 + j];
            const float lo = __int_as_float((b & 15)   | 0x4B000000) - 8388608.f;
            const float hi = __int_as_float((b & 0xF0) | 0x4B000000) - 8388608.f;
            bfr[1][j] = pkh2(fmaf(lo, A, B), fmaf(hi, A * 0.0625f, B));
        }

        const uint32_t su = xs_u32 + stage * STAGE_BYTES;
        const uint32_t lrow = (lane & 15) * 128 + (lane >> 4) * 16;
#pragma unroll
        for (int s = 0; s < 4; s++) {
            uint32_t a[4][4];
#pragma unroll
            for (int mt = 0; mt < 4; mt++)
                ldsm4(a[mt], su + swz(mt * 2048 + lrow + s * 32));
#pragma unroll
            for (int mt = 0; mt < 4; mt++) {
                mma16816(acc[mt][0], a[mt], bfr[0][2 * s], bfr[0][2 * s + 1]);
                mma16816(acc[mt][1], a[mt], bfr[1][2 * s], bfr[1][2 * s + 1]);
            }
        }
    };

    // prologue: stages for chunks 0..2 in flight, W prefetched distance 2
    ISSUE(0); cpa_commit();
    ISSUE(1); cpa_commit();
    ISSUE(2); cpa_commit();
    PrefW pa, pb;
    LOADW(0, pa);
    LOADW(1, pb);

#define STEP(c, P)                                              \
    do {                                                        \
        cpa_wait2();                                            \
        __syncthreads();                                        \
        COMPUTE(P, (c) & 3);                                    \
        if ((c) + 2 < NCHUNK) LOADW((c) + 2, P);                \
        if ((c) + 3 < NCHUNK) ISSUE((c) + 3);                   \
        cpa_commit();                                           \
    } while (0)

#pragma unroll 1
    for (int c = 0; c < NCHUNK; c += 2) {
        STEP(c, pa);
        if (c + 1 < NCHUNK) STEP(c + 1, pb);
    }
#undef STEP

    float* part = g_part[ks];
#pragma unroll
    for (int mt = 0; mt < 4; mt++) {
        const int m = mt * 16 + (lane >> 2);
#pragma unroll
        for (int nt = 0; nt < 2; nt++) {
            const int n = o0 + w * 16 + nt * 8 + (lane & 3) * 2;
            *(float2*)&part[m * OUT_F + n] =
                make_float2(acc[mt][nt][0], acc[mt][nt][1]);
            *(float2*)&part[(m + 8) * OUT_F + n] =
                make_float2(acc[mt][nt][2], acc[mt][nt][3]);
        }
    }
}

__global__ __launch_bounds__(256)
void convert_kernel(const float* __restrict__ x)
{
    const int i = blockIdx.x * 256 + threadIdx.x;      // 8 floats per thread
    const float4* p = (const float4*)x + i * 2;
    const float4 a = p[0], b = p[1];
    ((uint4*)g_xh)[i] = make_uint4(pkh2(a.x, a.y), pkh2(a.z, a.w),
                                   pkh2(b.x, b.y), pkh2(b.z, b.w));
}

__global__ __launch_bounds__(256)
void reduce_kernel(const float* __restrict__ bias, float* __restrict__ out)
{
    const int i = blockIdx.x * 256 + threadIdx.x;      // float4 index
    const float4 bb = ((const float4*)bias)[i & (OUT_F / 4 - 1)];
    float4 s = bb;
#pragma unroll
    for (int ks = 0; ks < KSPLIT; ks++) {
        const float4 p = ((const float4*)g_part[ks])[i];
        s.x += p.x; s.y += p.y; s.z += p.z; s.w += p.w;
    }
    ((float4*)out)[i] = s;
}

extern "C" void kernel_launch(void* const* d_in, const int* in_sizes, int n_in,
                              void* d_out, int out_size)
{
    const float* x      = (const float*)d_in[0];
    const int*   packed = (const int*)  d_in[1];
    const float* d      = (const float*)d_in[2];
    const float* dmin   = (const float*)d_in[3];
    const int*   scales = (const int*)  d_in[4];
    const int*   mins   = (const int*)  d_in[5];
    const float* bias   = (const float*)d_in[6];
    float* out = (float*)d_out;

    convert_kernel<<<(MROWS * IN_F / 8) / 256, 256>>>(x);
    qmma_kernel<<<NTILES * KSPLIT, THREADS>>>(packed, d, dmin, scales, mins);
    reduce_kernel<<<(MROWS * OUT_F / 4) / 256, 256>>>(bias, out);
}

// round 8
// speedup vs baseline: 4.7350x; 1.0325x over previous
#include <cuda_runtime.h>
#include <cuda_fp16.h>
#include <cstdint>

// y[64,4096] = x[64,11008] @ dequant(W)[4096,11008]^T + bias
// mma.sync.m16n8k16 f16/fp32. Barrier-free main loop:
//   x pre-packed into A-fragment layout (g_xfrag) -> LDG.128, no smem/ldmatrix.
//   W: LDG -> dequant -> B-fragments. Warp = (n16 slice, ks) unit.
// Grid: 64 o-tiles x KSPLIT(4) = 256 CTAs x 128 thr, occ 2 -> one wave.

#define OUT_F  4096
#define IN_F   11008
#define MROWS  64
#define KSPLIT 4
#define KC     (IN_F / KSPLIT)     // 2752
#define NSTEP  (KC / 32)           // 86 (one scale sub-block per step)
#define NKT    (IN_F / 16)         // 688 ktiles

__device__ float g_part[KSPLIT][MROWS * OUT_F];            // 4 MB
__device__ __align__(16) uint4 g_xfrag[NKT * 4 * 32];      // 1.4 MB A-fragments

__device__ __forceinline__ uint32_t pkh2(float lo, float hi) {
    uint32_t r;
    asm("cvt.rn.f16x2.f32 %0, %1, %2;" : "=r"(r) : "f"(hi), "f"(lo));
    return r;
}
__device__ __forceinline__ void mma16816(float* c, const uint32_t* a,
                                         uint32_t b0, uint32_t b1) {
    asm volatile(
        "mma.sync.aligned.m16n8k16.row.col.f32.f16.f16.f32 "
        "{%0,%1,%2,%3}, {%4,%5,%6,%7}, {%8,%9}, {%0,%1,%2,%3};"
        : "+f"(c[0]), "+f"(c[1]), "+f"(c[2]), "+f"(c[3])
        : "r"(a[0]), "r"(a[1]), "r"(a[2]), "r"(a[3]), "r"(b0), "r"(b1));
}

struct WB {                 // raw prefetched W data for one k32 step
    int   pw[8];            // 4 int32 per n8-row x 2 rows
    int   sc0, mn0, sc1, mn1;
    float d0, dm0, d1, dm1;
};

__global__ __launch_bounds__(128, 2)
void qmma_kernel(const int*   __restrict__ packed,
                 const float* __restrict__ d,
                 const float* __restrict__ dmin,
                 const int*   __restrict__ scales,
                 const int*   __restrict__ mins)
{
    const int t    = threadIdx.x;
    const int lane = t & 31;
    const int w    = t >> 5;                  // 4 warps, n16 each
    const int ob   = blockIdx.x & 63;         // 64-wide o tile
    const int ks   = blockIdx.x >> 6;
    const int o0   = ob * 64 + w * 16;
    const int kbase = ks * KC;
    const int kb16  = kbase >> 4;

    const int r0 = o0 + (lane >> 2);          // n-tile0 row; +8 = n-tile1
    const int kq = lane & 3;
    const int* prow0 = packed + r0 * (IN_F / 2) + (kbase >> 1) + kq;
    const int* prow1 = prow0 + 8 * (IN_F / 2);
    const uint4* xfl = g_xfrag + lane;

    float acc[4][2][4];
#pragma unroll
    for (int mt = 0; mt < 4; mt++)
#pragma unroll
        for (int nt = 0; nt < 2; nt++)
#pragma unroll
            for (int i = 0; i < 4; i++) acc[mt][nt][i] = 0.f;

    auto LOADW = [&](int s, WB& v) {
        const int* p0 = prow0 + s * 16;
        const int* p1 = prow1 + s * 16;
#pragma unroll
        for (int j = 0; j < 4; j++) {
            v.pw[j]     = __ldg(p0 + 4 * j);
            v.pw[4 + j] = __ldg(p1 + 4 * j);
        }
        const int j0 = r0 * IN_F + kbase + s * 32;
        const int j1 = j0 + 8 * IN_F;
        v.sc0 = __ldg(scales + (j0 >> 5)); v.mn0 = __ldg(mins + (j0 >> 5));
        v.d0  = __ldg(d + (j0 >> 8));      v.dm0 = __ldg(dmin + (j0 >> 8));
        v.sc1 = __ldg(scales + (j1 >> 5)); v.mn1 = __ldg(mins + (j1 >> 5));
        v.d1  = __ldg(d + (j1 >> 8));      v.dm1 = __ldg(dmin + (j1 >> 8));
    };

    auto LOADX = [&](int s, uint4* xv) {
        const int kt0 = kb16 + s * 2;
#pragma unroll
        for (int i = 0; i < 8; i++)
            xv[i] = __ldg(xfl + ((kt0 + (i >> 2)) * 4 + (i & 3)) * 32);
    };

    // one k32 step: dequant (consumes wv), prefetch W s+2, MMAs (consume xv),
    // prefetch x s+2
    auto STEP = [&](int s, WB& wv, uint4* xv) {
        const float A0 = wv.d0 * (float)wv.sc0 * (1.f / 945.f);
        const float B0 = fmaf(wv.d0, (float)wv.mn0 * (1.f / 63.f), wv.dm0);
        const float A1 = wv.d1 * (float)wv.sc1 * (1.f / 945.f);
        const float B1 = fmaf(wv.d1, (float)wv.mn1 * (1.f / 63.f), wv.dm1);
        const float Ah0 = A0 * 0.0625f, Ah1 = A1 * 0.0625f;

        uint32_t bf0[4], bf1[4];
#pragma unroll
        for (int j = 0; j < 4; j++) {
            int b = wv.pw[j];
            float lo = __int_as_float((b & 15)   | 0x4B000000) - 8388608.f;
            float hi = __int_as_float((b & 0xF0) | 0x4B000000) - 8388608.f;
            bf0[j] = pkh2(fmaf(lo, A0, B0), fmaf(hi, Ah0, B0));
            b = wv.pw[4 + j];
            lo = __int_as_float((b & 15)   | 0x4B000000) - 8388608.f;
            hi = __int_as_float((b & 0xF0) | 0x4B000000) - 8388608.f;
            bf1[j] = pkh2(fmaf(lo, A1, B1), fmaf(hi, Ah1, B1));
        }
        if (s + 2 < NSTEP) LOADW(s + 2, wv);    // W early: DRAM latency
#pragma unroll
        for (int s2 = 0; s2 < 2; s2++)
#pragma unroll
            for (int mt = 0; mt < 4; mt++) {
                const uint32_t* a = (const uint32_t*)&xv[s2 * 4 + mt];
                mma16816(acc[mt][0], a, bf0[2 * s2], bf0[2 * s2 + 1]);
                mma16816(acc[mt][1], a, bf1[2 * s2], bf1[2 * s2 + 1]);
            }
        if (s + 2 < NSTEP) LOADX(s + 2, xv);    // x: L2 hits
    };

    WB wa, wb;
    uint4 xa[8], xb[8];
    LOADW(0, wa); LOADX(0, xa);
    LOADW(1, wb); LOADX(1, xb);

#pragma unroll 1
    for (int s = 0; s < NSTEP; s += 2) {
        STEP(s, wa, xa);
        STEP(s + 1, wb, xb);
    }

    float* part = g_part[ks];
#pragma unroll
    for (int mt = 0; mt < 4; mt++) {
        const int m = mt * 16 + (lane >> 2);
#pragma unroll
        for (int nt = 0; nt < 2; nt++) {
            const int n = o0 + nt * 8 + (lane & 3) * 2;
            *(float2*)&part[m * OUT_F + n] =
                make_float2(acc[mt][nt][0], acc[mt][nt][1]);
            *(float2*)&part[(m + 8) * OUT_F + n] =
                make_float2(acc[mt][nt][2], acc[mt][nt][3]);
        }
    }
}

// pack x[64, IN_F] fp32 -> A-fragment layout (one uint4 per ktile/mtile/lane)
__global__ __launch_bounds__(256)
void convert_xfrag_kernel(const float* __restrict__ x)
{
    const int ti   = blockIdx.x * 256 + threadIdx.x;   // < NKT*4*32
    const int lane = ti & 31;
    const int mt   = (ti >> 5) & 3;
    const int kt   = ti >> 7;
    const int r = mt * 16 + (lane >> 2);
    const int c = kt * 16 + (lane & 3) * 2;
    const float* x0 = x + r * IN_F + c;
    const float* x1 = x0 + 8 * IN_F;
    const float2 a0 = *(const float2*)x0;
    const float2 a1 = *(const float2*)x1;
    const float2 a2 = *(const float2*)(x0 + 8);
    const float2 a3 = *(const float2*)(x1 + 8);
    g_xfrag[ti] = make_uint4(pkh2(a0.x, a0.y), pkh2(a1.x, a1.y),
                             pkh2(a2.x, a2.y), pkh2(a3.x, a3.y));
}

__global__ __launch_bounds__(256)
void reduce_kernel(const float* __restrict__ bias, float* __restrict__ out)
{
    const int i = blockIdx.x * 256 + threadIdx.x;      // float4 index
    const float4 bb = ((const float4*)bias)[i & (OUT_F / 4 - 1)];
    float4 s = bb;
#pragma unroll
    for (int ks = 0; ks < KSPLIT; ks++) {
        const float4 p = ((const float4*)g_part[ks])[i];
        s.x += p.x; s.y += p.y; s.z += p.z; s.w += p.w;
    }
    ((float4*)out)[i] = s;
}

extern "C" void kernel_launch(void* const* d_in, const int* in_sizes, int n_in,
                              void* d_out, int out_size)
{
    const float* x      = (const float*)d_in[0];
    const int*   packed = (const int*)  d_in[1];
    const float* d      = (const float*)d_in[2];
    const float* dmin   = (const float*)d_in[3];
    const int*   scales = (const int*)  d_in[4];
    const int*   mins   = (const int*)  d_in[5];
    const float* bias   = (const float*)d_in[6];
    float* out = (float*)d_out;

    convert_xfrag_kernel<<<(NKT * 4 * 32) / 256, 256>>>(x);
    qmma_kernel<<<64 * KSPLIT, 128>>>(packed, d, dmin, scales, mins);
    reduce_kernel<<<(MROWS * OUT_F / 4) / 256, 256>>>(bias, out);
}

// round 10
// speedup vs baseline: 6.1606x; 1.3011x over previous
#include <cuda_runtime.h>
#include <cuda_fp16.h>
#include <cstdint>

// y[64,4096] = x[64,11008] @ dequant(W)[4096,11008]^T + bias
// mma.sync.m16n8k16 f16/fp32, barrier-free. W: coalesced LDG.128 + quad byte
// transpose (shfl+prmt) -> B-fragments. Scales pre-folded to AB[sub][row].
// x pre-packed A-fragments (g_xfrag). Warp = n32 slice. KSPLIT=8.
// Grid: 32 o-tiles x 8 = 256 CTAs x 128 thr, occ 2, one wave.
// Dequant uses EXACT magic-bias subtraction (no folding into B -> no
// catastrophic cancellation).

#define OUT_F  4096
#define IN_F   11008
#define MROWS  64
#define KSPLIT 8
#define KC     (IN_F / KSPLIT)     // 1376
#define NSTEP  (KC / 32)           // 43
#define NSUB   (IN_F / 32)         // 344
#define NKT    (IN_F / 16)         // 688

__device__ float  g_part[KSPLIT][MROWS * OUT_F];       // 8 MB
__device__ __align__(16) uint4  g_xfrag[NKT * 4 * 32]; // 1.4 MB A-fragments
__device__ __align__(16) float2 g_ab[NSUB * OUT_F];    // 11 MB (A,B) coeffs

__device__ __forceinline__ uint32_t pkh2(float lo, float hi) {
    uint32_t r;
    asm("cvt.rn.f16x2.f32 %0, %1, %2;" : "=r"(r) : "f"(hi), "f"(lo));
    return r;
}
__device__ __forceinline__ void mma16816(float* c, const uint32_t* a,
                                         uint32_t b0, uint32_t b1) {
    asm volatile(
        "mma.sync.aligned.m16n8k16.row.col.f32.f16.f16.f32 "
        "{%0,%1,%2,%3}, {%4,%5,%6,%7}, {%8,%9}, {%0,%1,%2,%3};"
        : "+f"(c[0]), "+f"(c[1]), "+f"(c[2]), "+f"(c[3])
        : "r"(a[0]), "r"(a[1]), "r"(a[2]), "r"(a[3]), "r"(b0), "r"(b1));
}

struct WB {                // prefetched W data for one k32 step
    int4   wv[4];          // raw packed int32s, one int4 per n8 group
    float2 ab[4];          // (A, B) per n8 group
};

__global__ __launch_bounds__(128, 2)
void qmma_kernel(const int* __restrict__ packed)
{
    const int t    = threadIdx.x;
    const int lane = t & 31;
    const int w    = t >> 5;                 // 4 warps, n32 each
    const int ob   = blockIdx.x & 31;        // 128-wide o tile
    const int ks   = blockIdx.x >> 5;
    const int o0w  = ob * 128 + w * 32;
    const int kbase = ks * KC;

    const int q  = lane & 3;                 // quad index
    const int rq = lane >> 2;                // row-in-group 0..7

    // byte-transpose selectors (constant per lane)
    const uint32_t selA = 0x40 + q * 0x11;
    const uint32_t selR = (q & 1) ? ((q & 2) ? 0x0145u : 0x4501u)
                                  : ((q & 2) ? 0x1054u : 0x5410u);

    // W pointers: one per n8 group, lane reads contiguous int4
    const int* prow[4];
#pragma unroll
    for (int nt = 0; nt < 4; nt++)
        prow[nt] = packed + (o0w + 8 * nt + rq) * (IN_F / 2) + (kbase >> 1) + q * 4;
    const float2* abp = g_ab + (size_t)(ks * NSTEP) * OUT_F + o0w + rq;
    const uint4* xfl = g_xfrag + lane;
    const int kt0 = (kbase >> 4);

    float acc[4][4][4];
#pragma unroll
    for (int mt = 0; mt < 4; mt++)
#pragma unroll
        for (int nt = 0; nt < 4; nt++)
#pragma unroll
            for (int i = 0; i < 4; i++) acc[mt][nt][i] = 0.f;

    auto LOADW = [&](int s, WB& v) {
#pragma unroll
        for (int nt = 0; nt < 4; nt++)
            v.wv[nt] = __ldg((const int4*)(prow[nt] + s * 16));
#pragma unroll
        for (int nt = 0; nt < 4; nt++)
            v.ab[nt] = __ldg(abp + (size_t)s * OUT_F + 8 * nt);
    };
    auto LOADX = [&](int s, uint4* xv) {
        const int kt = kt0 + s * 2;
#pragma unroll
        for (int i = 0; i < 8; i++)
            xv[i] = __ldg(xfl + ((kt + (i >> 2)) * 4 + (i & 3)) * 32);
    };

    auto STEP = [&](int s, WB& wv, uint4* xv) {
        // quad transpose + dequant -> b-fragments h[nt][4]
        uint32_t h[4][4];
#pragma unroll
        for (int nt = 0; nt < 4; nt++) {
            const int4 v = wv.wv[nt];
            const uint32_t t01 = __byte_perm(v.x, v.y, 0x0040);
            const uint32_t t23 = __byte_perm(v.z, v.w, 0x0040);
            const uint32_t P   = __byte_perm(t01, t23, 0x5410);
            const uint32_t S1 = __shfl_xor_sync(0xffffffffu, P, 1);
            const uint32_t S2 = __shfl_xor_sync(0xffffffffu, P, 2);
            const uint32_t S3 = __shfl_xor_sync(0xffffffffu, P, 3);
            const uint32_t mA = __byte_perm(P,  S1, selA);
            const uint32_t mB = __byte_perm(S2, S3, selA);
            const uint32_t R  = __byte_perm(mA, mB, selR);
            const float A = wv.ab[nt].x;
            const float B = wv.ab[nt].y;
#pragma unroll
            for (int j = 0; j < 4; j++) {
                // exact: (2^23 + nib) - 2^23 has no rounding error
                const float lo = __int_as_float(((R >> (8 * j))     & 15) | 0x4B000000)
                                 - 8388608.f;
                const float hi = __int_as_float(((R >> (8 * j + 4)) & 15) | 0x4B000000)
                                 - 8388608.f;
                h[nt][j] = pkh2(fmaf(lo, A, B), fmaf(hi, A, B));
            }
        }
        if (s + 2 < NSTEP) LOADW(s + 2, wv);   // early: DRAM latency cover
#pragma unroll
        for (int tt = 0; tt < 2; tt++)
#pragma unroll
            for (int mt = 0; mt < 4; mt++) {
                const uint32_t* a = (const uint32_t*)&xv[tt * 4 + mt];
#pragma unroll
                for (int nt = 0; nt < 4; nt++)
                    mma16816(acc[mt][nt], a, h[nt][2 * tt], h[nt][2 * tt + 1]);
            }
        if (s + 2 < NSTEP) LOADX(s + 2, xv);
    };

    WB wa, wb;
    uint4 xa[8], xb[8];
    LOADW(0, wa); LOADX(0, xa);
    LOADW(1, wb); LOADX(1, xb);

#pragma unroll 1
    for (int s = 0; s < NSTEP - 1; s += 2) {
        STEP(s, wa, xa);
        STEP(s + 1, wb, xb);
    }
    STEP(NSTEP - 1, wa, xa);     // NSTEP odd: final step uses buffer a

    float* part = g_part[ks];
#pragma unroll
    for (int mt = 0; mt < 4; mt++) {
        const int m = mt * 16 + rq;
#pragma unroll
        for (int nt = 0; nt < 4; nt++) {
            const int n = o0w + nt * 8 + q * 2;
            *(float2*)&part[m * OUT_F + n] =
                make_float2(acc[mt][nt][0], acc[mt][nt][1]);
            *(float2*)&part[(m + 8) * OUT_F + n] =
                make_float2(acc[mt][nt][2], acc[mt][nt][3]);
        }
    }
}

// fold scales/mins/d/dmin into AB[sub][row] = (A, B), transposed via smem
__global__ __launch_bounds__(256)
void ab_kernel(const float* __restrict__ d,
               const float* __restrict__ dmin,
               const int*   __restrict__ scales,
               const int*   __restrict__ mins)
{
    __shared__ float2 tile[8][33];
    const int t  = threadIdx.x;
    const int r0 = (blockIdx.x & 127) * 32;       // row tile
    const int s0 = (blockIdx.x >> 7) * 8;         // sub tile
    {
        const int lr = t >> 3, lsu = t & 7;
        const int si = (r0 + lr) * NSUB + (s0 + lsu);
        const float dd = __ldg(d + (si >> 3));
        const float dm = __ldg(dmin + (si >> 3));
        const float A = dd * (float)__ldg(scales + si) * (1.f / 945.f);
        const float B = fmaf(dd, (float)__ldg(mins + si) * (1.f / 63.f), dm);
        tile[lsu][lr] = make_float2(A, B);
    }
    __syncthreads();
    {
        const int lsu = t >> 5, lr = t & 31;
        g_ab[(size_t)(s0 + lsu) * OUT_F + r0 + lr] = tile[lsu][lr];
    }
}

// pack x[64, IN_F] fp32 -> A-fragment layout
__global__ __launch_bounds__(256)
void convert_xfrag_kernel(const float* __restrict__ x)
{
    const int ti   = blockIdx.x * 256 + threadIdx.x;
    const int lane = ti & 31;
    const int mt   = (ti >> 5) & 3;
    const int kt   = ti >> 7;
    const int r = mt * 16 + (lane >> 2);
    const int c = kt * 16 + (lane & 3) * 2;
    const float* x0 = x + r * IN_F + c;
    const float* x1 = x0 + 8 * IN_F;
    const float2 a0 = *(const float2*)x0;
    const float2 a1 = *(const float2*)x1;
    const float2 a2 = *(const float2*)(x0 + 8);
    const float2 a3 = *(const float2*)(x1 + 8);
    g_xfrag[ti] = make_uint4(pkh2(a0.x, a0.y), pkh2(a1.x, a1.y),
                             pkh2(a2.x, a2.y), pkh2(a3.x, a3.y));
}

__global__ __launch_bounds__(256)
void reduce_kernel(const float* __restrict__ bias, float* __restrict__ out)
{
    const int i = blockIdx.x * 256 + threadIdx.x;      // float4 index
    const float4 bb = ((const float4*)bias)[i & (OUT_F / 4 - 1)];
    float4 s = bb;
#pragma unroll
    for (int ks = 0; ks < KSPLIT; ks++) {
        const float4 p = ((const float4*)g_part[ks])[i];
        s.x += p.x; s.y += p.y; s.z += p.z; s.w += p.w;
    }
    ((float4*)out)[i] = s;
}

extern "C" void kernel_launch(void* const* d_in, const int* in_sizes, int n_in,
                              void* d_out, int out_size)
{
    const float* x      = (const float*)d_in[0];
    const int*   packed = (const int*)  d_in[1];
    const float* d      = (const float*)d_in[2];
    const float* dmin   = (const float*)d_in[3];
    const int*   scales = (const int*)  d_in[4];
    const int*   mins   = (const int*)  d_in[5];
    const float* bias   = (const float*)d_in[6];
    float* out = (float*)d_out;

    convert_xfrag_kernel<<<(NKT * 4 * 32) / 256, 256>>>(x);
    ab_kernel<<<(OUT_F / 32) * (NSUB / 8), 256>>>(d, dmin, scales, mins);
    qmma_kernel<<<32 * KSPLIT, 128>>>(packed);
    reduce_kernel<<<(MROWS * OUT_F / 4) / 256, 256>>>(bias, out);
}

// round 11
// speedup vs baseline: 6.7703x; 1.0990x over previous
#include <cuda_runtime.h>
#include <cuda_fp16.h>
#include <cstdint>

// y[64,4096] = x[64,11008] @ dequant(W)[4096,11008]^T + bias
// mma.sync.m16n8k16 f16/fp32, barrier-free. W: coalesced LDG.128 (L1 evict_first)
// + quad byte transpose (shfl+prmt) -> B-fragments. AB[sub][row] pre-folded.
// x pre-packed A-fragments, loaded with L1 evict_last (4 warps/CTA share them).
// Warp = n32 slice. KSPLIT=8. Grid: 256 CTAs x 128 thr, occ 2, one wave.

#define OUT_F  4096
#define IN_F   11008
#define MROWS  64
#define KSPLIT 8
#define KC     (IN_F / KSPLIT)     // 1376
#define NSTEP  (KC / 32)           // 43
#define NSUB   (IN_F / 32)         // 344
#define NKT    (IN_F / 16)         // 688
#define XBLKS  86                  // prep: xfrag blocks (8 ktiles each)

__device__ float  g_part[KSPLIT][MROWS * OUT_F];       // 8 MB
__device__ __align__(16) uint4  g_xfrag[NKT * 4 * 32]; // 1.4 MB A-fragments
__device__ __align__(16) float2 g_ab[NSUB * OUT_F];    // 11 MB (A,B) coeffs

__device__ __forceinline__ uint32_t pkh2(float lo, float hi) {
    uint32_t r;
    asm("cvt.rn.f16x2.f32 %0, %1, %2;" : "=r"(r) : "f"(hi), "f"(lo));
    return r;
}
__device__ __forceinline__ void mma16816(float* c, const uint32_t* a,
                                         uint32_t b0, uint32_t b1) {
    asm volatile(
        "mma.sync.aligned.m16n8k16.row.col.f32.f16.f16.f32 "
        "{%0,%1,%2,%3}, {%4,%5,%6,%7}, {%8,%9}, {%0,%1,%2,%3};"
        : "+f"(c[0]), "+f"(c[1]), "+f"(c[2]), "+f"(c[3])
        : "r"(a[0]), "r"(a[1]), "r"(a[2]), "r"(a[3]), "r"(b0), "r"(b1));
}
// x fragments: keep in L1 (all 4 warps of the CTA reuse them)
__device__ __forceinline__ uint4 ldg_x(const uint4* p) {
    uint4 v;
    asm volatile("ld.global.nc.L1::evict_last.v4.u32 {%0,%1,%2,%3}, [%4];"
                 : "=r"(v.x), "=r"(v.y), "=r"(v.z), "=r"(v.w) : "l"(p));
    return v;
}
// W / AB: streaming, don't pollute L1
__device__ __forceinline__ int4 ldg_w(const int* p) {
    int4 v;
    asm volatile("ld.global.nc.L1::evict_first.v4.u32 {%0,%1,%2,%3}, [%4];"
                 : "=r"(v.x), "=r"(v.y), "=r"(v.z), "=r"(v.w) : "l"(p));
    return v;
}
__device__ __forceinline__ float2 ldg_ab(const float2* p) {
    float2 v;
    asm volatile("ld.global.nc.L1::evict_first.v2.f32 {%0,%1}, [%2];"
                 : "=f"(v.x), "=f"(v.y) : "l"(p));
    return v;
}

struct WB {                // prefetched W data for one k32 step
    int4   wv[4];          // raw packed int32s, one int4 per n8 group
    float2 ab[4];          // (A, B) per n8 group
};

__global__ __launch_bounds__(128, 2)
void qmma_kernel(const int* __restrict__ packed)
{
    const int t    = threadIdx.x;
    const int lane = t & 31;
    const int w    = t >> 5;                 // 4 warps, n32 each
    const int ob   = blockIdx.x & 31;        // 128-wide o tile
    const int ks   = blockIdx.x >> 5;
    const int o0w  = ob * 128 + w * 32;
    const int kbase = ks * KC;

    const int q  = lane & 3;                 // quad index
    const int rq = lane >> 2;                // row-in-group 0..7

    const uint32_t selA = 0x40 + q * 0x11;
    const uint32_t selR = (q & 1) ? ((q & 2) ? 0x0145u : 0x4501u)
                                  : ((q & 2) ? 0x1054u : 0x5410u);

    const int* prow[4];
#pragma unroll
    for (int nt = 0; nt < 4; nt++)
        prow[nt] = packed + (o0w + 8 * nt + rq) * (IN_F / 2) + (kbase >> 1) + q * 4;
    const float2* abp = g_ab + (size_t)(ks * NSTEP) * OUT_F + o0w + rq;
    const uint4* xfl = g_xfrag + lane;
    const int kt0 = (kbase >> 4);

    float acc[4][4][4];
#pragma unroll
    for (int mt = 0; mt < 4; mt++)
#pragma unroll
        for (int nt = 0; nt < 4; nt++)
#pragma unroll
            for (int i = 0; i < 4; i++) acc[mt][nt][i] = 0.f;

    auto LOADW = [&](int s, WB& v) {
#pragma unroll
        for (int nt = 0; nt < 4; nt++)
            v.wv[nt] = ldg_w(prow[nt] + s * 16);
#pragma unroll
        for (int nt = 0; nt < 4; nt++)
            v.ab[nt] = ldg_ab(abp + (size_t)s * OUT_F + 8 * nt);
    };
    auto LOADX = [&](int s, uint4* xv) {
        const int kt = kt0 + s * 2;
#pragma unroll
        for (int i = 0; i < 8; i++)
            xv[i] = ldg_x(xfl + ((kt + (i >> 2)) * 4 + (i & 3)) * 32);
    };

    auto STEP = [&](int s, WB& wv, uint4* xv) {
        uint32_t h[4][4];
#pragma unroll
        for (int nt = 0; nt < 4; nt++) {
            const int4 v = wv.wv[nt];
            const uint32_t t01 = __byte_perm(v.x, v.y, 0x0040);
            const uint32_t t23 = __byte_perm(v.z, v.w, 0x0040);
            const uint32_t P   = __byte_perm(t01, t23, 0x5410);
            const uint32_t S1 = __shfl_xor_sync(0xffffffffu, P, 1);
            const uint32_t S2 = __shfl_xor_sync(0xffffffffu, P, 2);
            const uint32_t S3 = __shfl_xor_sync(0xffffffffu, P, 3);
            const uint32_t mA = __byte_perm(P,  S1, selA);
            const uint32_t mB = __byte_perm(S2, S3, selA);
            const uint32_t R  = __byte_perm(mA, mB, selR);
            const float A = wv.ab[nt].x;
            const float B = wv.ab[nt].y;
#pragma unroll
            for (int j = 0; j < 4; j++) {
                // exact: (2^23 + nib) - 2^23 has no rounding error
                const float lo = __int_as_float(((R >> (8 * j))     & 15) | 0x4B000000)
                                 - 8388608.f;
                const float hi = __int_as_float(((R >> (8 * j + 4)) & 15) | 0x4B000000)
                                 - 8388608.f;
                h[nt][j] = pkh2(fmaf(lo, A, B), fmaf(hi, A, B));
            }
        }
        if (s + 2 < NSTEP) LOADW(s + 2, wv);   // early: DRAM latency cover
#pragma unroll
        for (int tt = 0; tt < 2; tt++)
#pragma unroll
            for (int mt = 0; mt < 4; mt++) {
                const uint32_t* a = (const uint32_t*)&xv[tt * 4 + mt];
#pragma unroll
                for (int nt = 0; nt < 4; nt++)
                    mma16816(acc[mt][nt], a, h[nt][2 * tt], h[nt][2 * tt + 1]);
            }
        if (s + 2 < NSTEP) LOADX(s + 2, xv);
    };

    WB wa, wb;
    uint4 xa[8], xb[8];
    LOADW(0, wa); LOADX(0, xa);
    LOADW(1, wb); LOADX(1, xb);

#pragma unroll 1
    for (int s = 0; s < NSTEP - 1; s += 2) {
        STEP(s, wa, xa);
        STEP(s + 1, wb, xb);
    }
    STEP(NSTEP - 1, wa, xa);     // NSTEP odd: final step uses buffer a

    float* part = g_part[ks];
#pragma unroll
    for (int mt = 0; mt < 4; mt++) {
        const int m = mt * 16 + rq;
#pragma unroll
        for (int nt = 0; nt < 4; nt++) {
            const int n = o0w + nt * 8 + q * 2;
            *(float2*)&part[m * OUT_F + n] =
                make_float2(acc[mt][nt][0], acc[mt][nt][1]);
            *(float2*)&part[(m + 8) * OUT_F + n] =
                make_float2(acc[mt][nt][2], acc[mt][nt][3]);
        }
    }
}

// merged prep: blocks [0, XBLKS) pack x into A-fragment layout via smem;
// blocks [XBLKS, ...) fold scales into g_ab with smem transpose.
__global__ __launch_bounds__(256)
void prep_kernel(const float* __restrict__ x,
                 const float* __restrict__ d,
                 const float* __restrict__ dmin,
                 const int*   __restrict__ scales,
                 const int*   __restrict__ mins)
{
    __shared__ __align__(16) char sbuf[64 * 68 * 4];   // 17.4 KB, both roles
    const int t = threadIdx.x;

    if (blockIdx.x < XBLKS) {
        // xfrag: block covers 8 ktiles = 128 columns, all 64 rows
        uint32_t (*smu)[68] = (uint32_t(*)[68])sbuf;   // stride 68 == 4 mod 32
        const int b = blockIdx.x;
        const float* xb = x + b * 128;
#pragma unroll
        for (int i = 0; i < 8; i++) {
            const int idx = t + i * 256;
            const int row = idx >> 5, c4 = idx & 31;
            const float4 v = *(const float4*)(xb + row * IN_F + c4 * 4);
            smu[row][c4 * 2]     = pkh2(v.x, v.y);
            smu[row][c4 * 2 + 1] = pkh2(v.z, v.w);
        }
        __syncthreads();
        uint4* outp = g_xfrag + b * (8 * 4 * 32);
#pragma unroll
        for (int i = 0; i < 4; i++) {
            const int idx  = t + i * 256;
            const int lane = idx & 31;
            const int mt   = (idx >> 5) & 3;
            const int ktl  = idx >> 7;
            const int r  = mt * 16 + (lane >> 2);
            const int ch = ktl * 8 + (lane & 3);     // f16x2-pair column
            outp[idx] = make_uint4(smu[r][ch],     smu[r + 8][ch],
                                   smu[r][ch + 4], smu[r + 8][ch + 4]);
        }
    } else {
        float2 (*tile)[33] = (float2(*)[33])sbuf;
        const int bb = blockIdx.x - XBLKS;
        const int r0 = (bb & 127) * 32;       // row tile
        const int s0 = (bb >> 7) * 8;         // sub tile
        {
            const int lr = t >> 3, lsu = t & 7;
            const int si = (r0 + lr) * NSUB + (s0 + lsu);
            const float dd = __ldg(d + (si >> 3));
            const float dm = __ldg(dmin + (si >> 3));
            const float A = dd * (float)__ldg(scales + si) * (1.f / 945.f);
            const float B = fmaf(dd, (float)__ldg(mins + si) * (1.f / 63.f), dm);
            tile[lsu][lr] = make_float2(A, B);
        }
        __syncthreads();
        {
            const int lsu = t >> 5, lr = t & 31;
            g_ab[(size_t)(s0 + lsu) * OUT_F + r0 + lr] = tile[lsu][lr];
        }
    }
}

__global__ __launch_bounds__(128)
void reduce_kernel(const float* __restrict__ bias, float* __restrict__ out)
{
    const int i = blockIdx.x * 128 + threadIdx.x;      // float4 index
    const float4 bb = ((const float4*)bias)[i & (OUT_F / 4 - 1)];
    float4 s = bb;
#pragma unroll
    for (int ks = 0; ks < KSPLIT; ks++) {
        const float4 p = ((const float4*)g_part[ks])[i];
        s.x += p.x; s.y += p.y; s.z += p.z; s.w += p.w;
    }
    ((float4*)out)[i] = s;
}

extern "C" void kernel_launch(void* const* d_in, const int* in_sizes, int n_in,
                              void* d_out, int out_size)
{
    const float* x      = (const float*)d_in[0];
    const int*   packed = (const int*)  d_in[1];
    const float* d      = (const float*)d_in[2];
    const float* dmin   = (const float*)d_in[3];
    const int*   scales = (const int*)  d_in[4];
    const int*   mins   = (const int*)  d_in[5];
    const float* bias   = (const float*)d_in[6];
    float* out = (float*)d_out;

    prep_kernel<<<XBLKS + (OUT_F / 32) * (NSUB / 8), 256>>>(x, d, dmin, scales, mins);
    qmma_kernel<<<32 * KSPLIT, 128>>>(packed);
    reduce_kernel<<<(MROWS * OUT_F / 4) / 128, 128>>>(bias, out);
}